// round 10
// baseline (speedup 1.0000x reference)
#include <cuda_runtime.h>
#include <math.h>

// Problem constants (fixed by setup_inputs)
#define BATCH 2
#define HH    120
#define WW    160
#define PLANE (HH*WW)          // 19200
#define NP    (BATCH*PLANE)    // 38400

// ---------------- scratch (device globals; no allocation allowed) ----------
__device__ float g_cd [BATCH*16 *PLANE];
__device__ float g_bst[NP];
__device__ float g_bsp[NP];
__device__ float g_t1 [BATCH*128*PLANE];
__device__ float g_t2 [BATCH*128*PLANE];
__device__ float g_dd [BATCH*256*PLANE];
__device__ float g_ha [BATCH*128*PLANE];
__device__ float g_hb [BATCH*128*PLANE];
__device__ float g_zb [BATCH*128*PLANE];
__device__ float g_rb [BATCH*128*PLANE];   // holds r*h after fused zr kernel
__device__ float g_pb [BATCH*16 *PLANE];
// precomputed context partial sums (loop-invariant)
__device__ float g_pzr1[BATCH*256*PLANE];
__device__ float g_pq1 [BATCH*128*PLANE];
__device__ float g_pzr2[BATCH*256*PLANE];
__device__ float g_pq2 [BATCH*128*PLANE];
// transposed weights, layout [ci][khkw][coStride], one region per conv
__device__ __align__(16) float g_wt[3067904];

// region offsets inside g_wt (floats)
#define OFF_E1  0
#define OFF_E2  100352
#define OFF_E3  247808
#define OFF_E4  395264
#define OFF_ZR1 690176      // z1|r1 interleaved, stride 256
#define OFF_Q1  1427456
#define OFF_ZR2 1796096     // z2|r2 interleaved, stride 256
#define OFF_Q2  2533376
#define OFF_P1  2902016
#define OFF_P2  3049472

// ---------------- f32x2 / cp.async helpers ---------------------------------
__device__ __forceinline__ unsigned long long fma2(unsigned long long a,
                                                   unsigned long long b,
                                                   unsigned long long c) {
    unsigned long long d;
    asm("fma.rn.f32x2 %0, %1, %2, %3;" : "=l"(d) : "l"(a), "l"(b), "l"(c));
    return d;
}
__device__ __forceinline__ unsigned long long splat2(float x) {
    unsigned long long d;
    asm("mov.b64 %0, {%1, %1};" : "=l"(d) : "f"(x));
    return d;
}
__device__ __forceinline__ float lo32(unsigned long long v) {
    return __uint_as_float((unsigned)(v & 0xffffffffull));
}
__device__ __forceinline__ float hi32(unsigned long long v) {
    return __uint_as_float((unsigned)(v >> 32));
}
__device__ __forceinline__ unsigned smaddr(const void* p) {
    return (unsigned)__cvta_generic_to_shared(p);
}
__device__ __forceinline__ void cpa4(unsigned d, const float* s, int sz) {
    asm volatile("cp.async.ca.shared.global [%0], [%1], 4, %2;"
                 :: "r"(d), "l"(s), "r"(sz));
}
__device__ __forceinline__ void cpa16(unsigned d, const float* s, int sz) {
    asm volatile("cp.async.cg.shared.global [%0], [%1], 16, %2;"
                 :: "r"(d), "l"(s), "r"(sz));
}
__device__ __forceinline__ void cpa_commit() {
    asm volatile("cp.async.commit_group;");
}

// ------- weight transpose: [co][ci][r] -> [ci][r][stride] with offset -------
__global__ void transp_k(const float* __restrict__ src, float* __restrict__ dst,
                         int Cout, int Cin, int KK, int stride, int off)
{
    const int idx = blockIdx.x * blockDim.x + threadIdx.x;
    const int total = Cout * Cin * KK;
    if (idx >= total) return;
    const int co  = idx / (Cin * KK);
    const int rem = idx - co * (Cin * KK);
    dst[(size_t)rem * stride + off + co] = src[idx];
}

// ---------------- generic direct conv, 2 rows/block, cp.async pipeline ------
// block = 128 threads, TM=64 out-ch x TN=32 px x 2 rows; thread tile
// 4co x 4px x 2rows, co-pairs packed in f32x2. Double-buffered cp.async
// staging. Grid-stride loop over flattened (b, cotile, tile) work items so
// every launch is a SINGLE wave with equal tiles per block (no tail waves).
// MINB = min blocks/SM hint. ACT: 0 none, 1 relu, 2 sigmoid,
// 3 GRU blend (1-z)*hprev + z*tanh(v),
// 4 split: co<128 -> sigmoid -> outp (z); co>=128 -> sigmoid*hprev -> outp2 (r*h).
constexpr int TM = 64, TN = 32;
#define NTILE 300   // 5 x-tiles * 60 row-pairs

template<int KH, int KW, int ACT, int MINB>
__global__ __launch_bounds__(128, MINB)
void conv_k(const float* __restrict__ in0, int c0,
            const float* __restrict__ in1, int c1,
            const float* __restrict__ in2, int c2,
            const float* __restrict__ wt,    // transposed [ci][khkw][Cout]
            const float* __restrict__ bias,
            const float* __restrict__ bias2,
            const float* __restrict__ pre,
            const float* __restrict__ zbuf,
            const float* __restrict__ hprev,
            float* __restrict__ outp,
            float* __restrict__ outp2, int Cout, int Cin,
            int total, int ncot)
{
    constexpr int KK  = KH * KW;
    constexpr int CK  = (KK > 25) ? 1 : 8;
    constexpr int PH  = KH / 2;
    constexpr int PW  = KW / 2;
    constexpr int WIN = 4 + KW - 1;
    constexpr int NW4 = (WIN + 3) / 4;
    constexpr int TNP = 28 + NW4 * 4;
    constexpr int NR  = KH + 1;

    __shared__ __align__(16) float s_w [2][CK * KK * TM];
    __shared__ __align__(16) float s_in[2][CK * NR * TNP];

    const int tid = threadIdx.x;
    const int tco = tid >> 3;     // 0..15
    const int tpx = tid & 7;      // 0..7
    const int nch = Cin / CK;

    for (int t = blockIdx.x; t < total; t += gridDim.x) {
        const int tile   = t % NTILE;
        const int rest   = t / NTILE;
        const int cotile = rest % ncot;
        const int b      = rest / ncot;
        const int y0     = (tile / (WW / TN)) * 2;
        const int x0     = (tile % (WW / TN)) * TN;
        const int cob    = cotile * TM;

        // -------- stage one chunk into buffer `buf` via cp.async --------
        auto stage = [&](int ci0, int buf) {
            const float* src; int ct, cl;
            if (ci0 < c0)           { src = in0; ct = c0; cl = ci0;           }
            else if (ci0 < c0 + c1) { src = in1; ct = c1; cl = ci0 - c0;      }
            else                    { src = in2; ct = c2; cl = ci0 - c0 - c1; }
            const float* sb = src + ((size_t)b * ct + cl) * PLANE;
            for (int i = tid; i < CK * NR * TNP; i += 128) {
                const int ci  = i / (NR * TNP);
                const int rem = i - ci * (NR * TNP);
                const int rr  = rem / TNP;
                const int j   = rem - rr * TNP;
                const int yy  = y0 - PH + rr;
                const int xx  = x0 - PW + j;
                const bool inb = (yy >= 0 && yy < HH && xx >= 0 && xx < WW);
                const size_t o = inb ? ((size_t)ci * PLANE + yy * WW + xx) : 0;
                cpa4(smaddr(&s_in[buf][i]), sb + o, inb ? 4 : 0);
            }
            for (int i4 = tid; i4 < CK * KK * (TM / 4); i4 += 128) {
                const int co4 = (i4 & 15) * 4;
                const int r   = i4 >> 4;
                const int gco = cob + co4;
                const float* wrow = wt + ((size_t)ci0 * KK + r) * Cout + gco;
                cpa16(smaddr(&s_w[buf][r * TM + co4]), wrow, (gco < Cout) ? 16 : 0);
            }
            cpa_commit();
        };

        unsigned long long acc[2][4][2];
#pragma unroll
        for (int r = 0; r < 2; r++)
#pragma unroll
            for (int i = 0; i < 4; i++) { acc[r][i][0] = 0ull; acc[r][i][1] = 0ull; }

        stage(0, 0);

        for (int c = 0; c < nch; c++) {
            if (c + 1 < nch) {
                stage((c + 1) * CK, (c + 1) & 1);
                asm volatile("cp.async.wait_group 1;");
            } else {
                asm volatile("cp.async.wait_group 0;");
            }
            __syncthreads();

            const float* sw  = s_w [c & 1];
            const float* sin = s_in[c & 1];

            for (int ci = 0; ci < CK; ci++) {
                unsigned long long sp[2][WIN];
                {
                    const float* ip = sin + (ci * NR + 0) * TNP + tpx * 4;
                    float win[NW4 * 4];
#pragma unroll
                    for (int w4 = 0; w4 < NW4; w4++)
                        *(float4*)(win + 4 * w4) = *(const float4*)(ip + 4 * w4);
#pragma unroll
                    for (int j = 0; j < WIN; j++) sp[0][j] = splat2(win[j]);
                }
#pragma unroll
                for (int kh = 0; kh < KH; kh++) {
                    {
                        const float* ip = sin + (ci * NR + kh + 1) * TNP + tpx * 4;
                        float win[NW4 * 4];
#pragma unroll
                        for (int w4 = 0; w4 < NW4; w4++)
                            *(float4*)(win + 4 * w4) = *(const float4*)(ip + 4 * w4);
#pragma unroll
                        for (int j = 0; j < WIN; j++) sp[(kh + 1) & 1][j] = splat2(win[j]);
                    }
                    const unsigned long long* s0 = sp[kh & 1];
                    const unsigned long long* s1 = sp[(kh + 1) & 1];
#pragma unroll
                    for (int kw = 0; kw < KW; kw++) {
                        const ulonglong2 wv = *(const ulonglong2*)
                            (sw + ((ci * KH + kh) * KW + kw) * TM + tco * 4);
#pragma unroll
                        for (int rn = 0; rn < 4; rn++) {
                            acc[0][rn][0] = fma2(wv.x, s0[kw + rn], acc[0][rn][0]);
                            acc[0][rn][1] = fma2(wv.y, s0[kw + rn], acc[0][rn][1]);
                            acc[1][rn][0] = fma2(wv.x, s1[kw + rn], acc[1][rn][0]);
                            acc[1][rn][1] = fma2(wv.y, s1[kw + rn], acc[1][rn][1]);
                        }
                    }
                }
            }
            __syncthreads();
        }

        // -------- epilogue (2 rows) --------
#pragma unroll
        for (int row = 0; row < 2; row++) {
            const int y = y0 + row;
#pragma unroll
            for (int rn = 0; rn < 4; rn++) {
                float vals[4] = { lo32(acc[row][rn][0]), hi32(acc[row][rn][0]),
                                  lo32(acc[row][rn][1]), hi32(acc[row][rn][1]) };
                const int x = x0 + tpx * 4 + rn;
                const int pix = y * WW + x;
#pragma unroll
                for (int rm = 0; rm < 4; rm++) {
                    const int co = cob + tco * 4 + rm;
                    if (co >= Cout) continue;
                    float v = vals[rm];
                    if (pre) v += pre[((size_t)b * Cout + co) * PLANE + pix];
                    if (ACT == 4) {
                        if (co < 128) {
                            v += bias[co];
                            v = 1.f / (1.f + expf(-v));
                            outp[((size_t)b * 128 + co) * PLANE + pix] = v;
                        } else {
                            v += bias2[co - 128];
                            v = 1.f / (1.f + expf(-v));
                            const size_t hi = ((size_t)b * 128 + (co - 128)) * PLANE + pix;
                            outp2[hi] = v * hprev[hi];   // write r*h directly
                        }
                    } else {
                        if (bias) v += bias[co];
                        const size_t oi = ((size_t)b * Cout + co) * PLANE + pix;
                        if (ACT == 1) {
                            v = fmaxf(v, 0.f);
                        } else if (ACT == 2) {
                            v = 1.f / (1.f + expf(-v));
                        } else if (ACT == 3) {
                            const size_t hi = ((size_t)b * 128 + co) * PLANE + pix;
                            const float z  = zbuf[hi];
                            const float hp = hprev[hi];
                            v = (1.f - z) * hp + z * tanhf(v);
                        }
                        outp[oi] = v;
                    }
                }
            }
        }
    }
}

// ---------------- init: uniform bins, cd midpoints --------------------------
__global__ void init_k(float* __restrict__ cd, float* __restrict__ bst,
                       float* __restrict__ bsp)
{
    const int p = blockIdx.x * blockDim.x + threadIdx.x;
    if (p >= NP) return;
    bst[p] = 0.f;
    bsp[p] = 5.f;
    const int b  = p / PLANE;
    const int pp = p - b * PLANE;
    float e = 0.f;
#pragma unroll
    for (int i = 0; i < 16; i++) {
        const float en = e + 5.f;
        cd[((size_t)b * 16 + i) * PLANE + pp] = 0.5f * (e + en);
        e = en;
    }
}

// ---------------- epilogue: softmax, stats, label, bin update ---------------
__device__ __forceinline__ float clip80(float v) {
    return fminf(fmaxf(v, 0.f), 80.f);
}

__global__ void epi_k(const float* __restrict__ lg, float* __restrict__ cd,
                      float* __restrict__ bst, float* __restrict__ bsp,
                      float* __restrict__ outp, int iter)
{
    const int p = blockIdx.x * blockDim.x + threadIdx.x;
    if (p >= NP) return;
    const int b  = p / PLANE;
    const int pp = p - b * PLANE;
    const float* l0 = lg + (size_t)b * 16 * PLANE + pp;
    float*       c0 = cd + (size_t)b * 16 * PLANE + pp;

    float l[16], c[16];
    float m = -1e30f;
#pragma unroll
    for (int i = 0; i < 16; i++) { l[i] = l0[i * PLANE]; m = fmaxf(m, l[i]); }
    float s = 0.f;
#pragma unroll
    for (int i = 0; i < 16; i++) { l[i] = expf(l[i] - m); s += l[i]; }
    const float inv = 1.f / s;
    float dr = 0.f;
#pragma unroll
    for (int i = 0; i < 16; i++) { c[i] = c0[i * PLANE]; dr += l[i] * inv * c[i]; }
    float var = 0.f;
#pragma unroll
    for (int i = 0; i < 16; i++) { const float d = c[i] - dr; var += l[i] * inv * d * d; }
    const float unc = sqrtf(var);

    const float st = bst[p], sp = bsp[p];
    int cnt = 0;
    float e = st;
#pragma unroll
    for (int i = 1; i <= 15; i++) { e += sp; cnt += (dr >= clip80(e)) ? 1 : 0; }
    e += sp;
    const int label = (dr >= clip80(e)) ? 0 : cnt;
    const float cs = c[label];

    outp[(0 * 6 + iter) * NP + p] = dr;
    outp[(1 * 6 + iter) * NP + p] = cs;
    outp[(2 * 6 + iter) * NP + p] = unc;

    const float nst = fmaxf(dr - 0.5f * unc, 0.f);
    const float nsp = unc * (1.f / 16.f);
    bst[p] = nst;
    bsp[p] = nsp;
    float ep   = clip80(nst);
    float ecur = nst;
#pragma unroll
    for (int i = 0; i < 16; i++) {
        ecur += nsp;
        const float ec = clip80(ecur);
        c0[i * PLANE] = 0.5f * (ep + ec);
        ep = ec;
    }
}

// ---------------- host ------------------------------------------------------
static void do_transp(const float* src, float* dst, int Cout, int Cin, int KK,
                      int stride, int off) {
    const int total = Cout * Cin * KK;
    transp_k<<<(total + 255) / 256, 256>>>(src, dst, Cout, Cin, KK, stride, off);
}

// largest G = total/k with G <= cap (exact division; totals are 600/1200/2400)
static int pick_grid(int total, int cap) {
    for (int k = 1; k <= total; k++)
        if (total % k == 0 && total / k <= cap) return total / k;
    return cap;
}

extern "C" void kernel_launch(void* const* d_in, const int* in_sizes, int n_in,
                              void* d_out, int out_size)
{
    (void)in_sizes; (void)n_in; (void)out_size;
    const float* ctx  = (const float*)d_in[1];
    const float* gruh = (const float*)d_in[2];
    const float* w_e1 = (const float*)d_in[3];  const float* b_e1 = (const float*)d_in[4];
    const float* w_e2 = (const float*)d_in[5];  const float* b_e2 = (const float*)d_in[6];
    const float* w_e3 = (const float*)d_in[7];  const float* b_e3 = (const float*)d_in[8];
    const float* w_e4 = (const float*)d_in[9];  const float* b_e4 = (const float*)d_in[10];
    const float* w_z1 = (const float*)d_in[11]; const float* b_z1 = (const float*)d_in[12];
    const float* w_r1 = (const float*)d_in[13]; const float* b_r1 = (const float*)d_in[14];
    const float* w_q1 = (const float*)d_in[15]; const float* b_q1 = (const float*)d_in[16];
    const float* w_z2 = (const float*)d_in[17]; const float* b_z2 = (const float*)d_in[18];
    const float* w_r2 = (const float*)d_in[19]; const float* b_r2 = (const float*)d_in[20];
    const float* w_q2 = (const float*)d_in[21]; const float* b_q2 = (const float*)d_in[22];
    const float* w_p1 = (const float*)d_in[23]; const float* b_p1 = (const float*)d_in[24];
    const float* w_p2 = (const float*)d_in[25]; const float* b_p2 = (const float*)d_in[26];

    float *cd, *bst, *bsp, *t1, *t2, *dd, *ha, *hb, *zb, *rb, *pb, *wt;
    float *pzr1, *pq1, *pzr2, *pq2;
    cudaGetSymbolAddress((void**)&cd,  g_cd);
    cudaGetSymbolAddress((void**)&bst, g_bst);
    cudaGetSymbolAddress((void**)&bsp, g_bsp);
    cudaGetSymbolAddress((void**)&t1,  g_t1);
    cudaGetSymbolAddress((void**)&t2,  g_t2);
    cudaGetSymbolAddress((void**)&dd,  g_dd);
    cudaGetSymbolAddress((void**)&ha,  g_ha);
    cudaGetSymbolAddress((void**)&hb,  g_hb);
    cudaGetSymbolAddress((void**)&zb,  g_zb);
    cudaGetSymbolAddress((void**)&rb,  g_rb);
    cudaGetSymbolAddress((void**)&pb,  g_pb);
    cudaGetSymbolAddress((void**)&wt,  g_wt);
    cudaGetSymbolAddress((void**)&pzr1, g_pzr1);
    cudaGetSymbolAddress((void**)&pq1,  g_pq1);
    cudaGetSymbolAddress((void**)&pzr2, g_pzr2);
    cudaGetSymbolAddress((void**)&pq2,  g_pq2);
    float* out = (float*)d_out;

    // weight transposes (z/r interleaved into stride-256 regions)
    do_transp(w_e1, wt + OFF_E1, 128, 16, 49, 128, 0);
    do_transp(w_e2, wt + OFF_E2, 128, 128, 9, 128, 0);
    do_transp(w_e3, wt + OFF_E3, 128, 128, 9, 128, 0);
    do_transp(w_e4, wt + OFF_E4, 256, 128, 9, 256, 0);
    do_transp(w_z1, wt + OFF_ZR1, 128, 576, 5, 256, 0);
    do_transp(w_r1, wt + OFF_ZR1, 128, 576, 5, 256, 128);
    do_transp(w_q1, wt + OFF_Q1, 128, 576, 5, 128, 0);
    do_transp(w_z2, wt + OFF_ZR2, 128, 576, 5, 256, 0);
    do_transp(w_r2, wt + OFF_ZR2, 128, 576, 5, 256, 128);
    do_transp(w_q2, wt + OFF_Q2, 128, 576, 5, 128, 0);
    do_transp(w_p1, wt + OFF_P1, 128, 128, 9, 128, 0);
    do_transp(w_p2, wt + OFF_P2, 16, 128, 9, 16, 0);

    cudaMemcpyAsync(ha, gruh, sizeof(float) * BATCH * 128 * PLANE,
                    cudaMemcpyDeviceToDevice, 0);
    init_k<<<(NP + 255) / 256, 256>>>(cd, bst, bsp);

    // totals: NTILE * ncot * BATCH;  caps: 148 * MINB
    const int T1 = NTILE * 1 * BATCH;   // 600
    const int T2 = NTILE * 2 * BATCH;   // 1200
    const int T4 = NTILE * 4 * BATCH;   // 2400
    const int G2_4 = pick_grid(T2, 592);   // 400  (x3)
    const int G4_4 = pick_grid(T4, 592);   // 480  (x5)
    const int G1_5 = pick_grid(T1, 740);   // 600  (x1)
    const int G2_5 = pick_grid(T2, 740);   // 600  (x2)
    const int G4_5 = pick_grid(T4, 740);   // 600  (x4)

    // ---- loop-invariant ctx partial sums (192 of the 576 GRU channels) ----
    conv_k<1, 5, 0, 4><<<G4_4, 128>>>(ctx, 192, nullptr, 0, nullptr, 0,
                                 wt + OFF_ZR1 + (size_t)384 * 5 * 256,
                                 nullptr, nullptr, nullptr, nullptr, nullptr,
                                 pzr1, nullptr, 256, 192, T4, 4);
    conv_k<1, 5, 0, 4><<<G2_4, 128>>>(ctx, 192, nullptr, 0, nullptr, 0,
                                 wt + OFF_Q1 + (size_t)384 * 5 * 128,
                                 nullptr, nullptr, nullptr, nullptr, nullptr,
                                 pq1, nullptr, 128, 192, T2, 2);
    conv_k<5, 1, 0, 5><<<G4_5, 128>>>(ctx, 192, nullptr, 0, nullptr, 0,
                                 wt + OFF_ZR2 + (size_t)384 * 5 * 256,
                                 nullptr, nullptr, nullptr, nullptr, nullptr,
                                 pzr2, nullptr, 256, 192, T4, 4);
    conv_k<5, 1, 0, 5><<<G2_5, 128>>>(ctx, 192, nullptr, 0, nullptr, 0,
                                 wt + OFF_Q2 + (size_t)384 * 5 * 128,
                                 nullptr, nullptr, nullptr, nullptr, nullptr,
                                 pq2, nullptr, 128, 192, T2, 2);

    for (int it = 0; it < 6; it++) {
        // depth encoder
        conv_k<7, 7, 1, 4><<<G2_4, 128>>>(cd, 16, nullptr, 0, nullptr, 0,
                                     wt + OFF_E1, b_e1, nullptr, nullptr,
                                     nullptr, nullptr, t1, nullptr, 128, 16, T2, 2);
        conv_k<3, 3, 1, 5><<<G2_5, 128>>>(t1, 128, nullptr, 0, nullptr, 0,
                                     wt + OFF_E2, b_e2, nullptr, nullptr,
                                     nullptr, nullptr, t2, nullptr, 128, 128, T2, 2);
        conv_k<3, 3, 1, 5><<<G2_5, 128>>>(t2, 128, nullptr, 0, nullptr, 0,
                                     wt + OFF_E3, b_e3, nullptr, nullptr,
                                     nullptr, nullptr, t1, nullptr, 128, 128, T2, 2);
        conv_k<3, 3, 1, 5><<<G4_5, 128>>>(t1, 128, nullptr, 0, nullptr, 0,
                                     wt + OFF_E4, b_e4, nullptr, nullptr,
                                     nullptr, nullptr, dd, nullptr, 256, 128, T4, 4);
        // GRU horizontal (1x5): fused z|r (r*h written to rb), then q
        conv_k<1, 5, 4, 4><<<G4_4, 128>>>(ha, 128, dd, 256, nullptr, 0,
                                     wt + OFF_ZR1, b_z1, b_r1, pzr1,
                                     nullptr, ha, zb, rb, 256, 384, T4, 4);
        conv_k<1, 5, 3, 4><<<G2_4, 128>>>(rb, 128, dd, 256, nullptr, 0,
                                     wt + OFF_Q1, b_q1, nullptr, pq1,
                                     zb, ha, hb, nullptr, 128, 384, T2, 2);
        // GRU vertical (5x1): reads hb, writes ha
        conv_k<5, 1, 4, 5><<<G4_5, 128>>>(hb, 128, dd, 256, nullptr, 0,
                                     wt + OFF_ZR2, b_z2, b_r2, pzr2,
                                     nullptr, hb, zb, rb, 256, 384, T4, 4);
        conv_k<5, 1, 3, 5><<<G2_5, 128>>>(rb, 128, dd, 256, nullptr, 0,
                                     wt + OFF_Q2, b_q2, nullptr, pq2,
                                     zb, hb, ha, nullptr, 128, 384, T2, 2);
        // PHead
        conv_k<3, 3, 1, 5><<<G2_5, 128>>>(ha, 128, nullptr, 0, nullptr, 0,
                                     wt + OFF_P1, b_p1, nullptr, nullptr,
                                     nullptr, nullptr, t1, nullptr, 128, 128, T2, 2);
        conv_k<3, 3, 0, 5><<<G1_5, 128>>>(t1, 128, nullptr, 0, nullptr, 0,
                                     wt + OFF_P2, b_p2, nullptr, nullptr,
                                     nullptr, nullptr, pb, nullptr, 16, 128, T1, 1);
        epi_k<<<(NP + 255) / 256, 256>>>(pb, cd, bst, bsp, out, it);
    }
}

// round 11
// speedup vs baseline: 1.8967x; 1.8967x over previous
#include <cuda_runtime.h>
#include <math.h>

// Problem constants (fixed by setup_inputs)
#define BATCH 2
#define HH    120
#define WW    160
#define PLANE (HH*WW)          // 19200
#define NP    (BATCH*PLANE)    // 38400

// ---------------- scratch (device globals; no allocation allowed) ----------
__device__ float g_cd [BATCH*16 *PLANE];
__device__ float g_bst[NP];
__device__ float g_bsp[NP];
__device__ float g_t1 [BATCH*128*PLANE];
__device__ float g_t2 [BATCH*128*PLANE];
__device__ float g_dd [BATCH*256*PLANE];
__device__ float g_ha [BATCH*128*PLANE];
__device__ float g_hb [BATCH*128*PLANE];
__device__ float g_zb [BATCH*128*PLANE];
__device__ float g_rb [BATCH*128*PLANE];   // holds r*h after fused zr kernel
__device__ float g_pb [BATCH*16 *PLANE];
// precomputed context partial sums (loop-invariant)
__device__ float g_pzr1[BATCH*256*PLANE];
__device__ float g_pq1 [BATCH*128*PLANE];
__device__ float g_pzr2[BATCH*256*PLANE];
__device__ float g_pq2 [BATCH*128*PLANE];
// transposed weights, layout [ci][khkw][coStride], one region per conv
__device__ __align__(16) float g_wt[3067904];

// region offsets inside g_wt (floats)
#define OFF_E1  0
#define OFF_E2  100352
#define OFF_E3  247808
#define OFF_E4  395264
#define OFF_ZR1 690176      // z1|r1 interleaved, stride 256
#define OFF_Q1  1427456
#define OFF_ZR2 1796096     // z2|r2 interleaved, stride 256
#define OFF_Q2  2533376
#define OFF_P1  2902016
#define OFF_P2  3049472

// ---------------- f32x2 / cp.async helpers ---------------------------------
__device__ __forceinline__ unsigned long long fma2(unsigned long long a,
                                                   unsigned long long b,
                                                   unsigned long long c) {
    unsigned long long d;
    asm("fma.rn.f32x2 %0, %1, %2, %3;" : "=l"(d) : "l"(a), "l"(b), "l"(c));
    return d;
}
__device__ __forceinline__ unsigned long long splat2(float x) {
    unsigned long long d;
    asm("mov.b64 %0, {%1, %1};" : "=l"(d) : "f"(x));
    return d;
}
__device__ __forceinline__ float lo32(unsigned long long v) {
    return __uint_as_float((unsigned)(v & 0xffffffffull));
}
__device__ __forceinline__ float hi32(unsigned long long v) {
    return __uint_as_float((unsigned)(v >> 32));
}
__device__ __forceinline__ unsigned smaddr(const void* p) {
    return (unsigned)__cvta_generic_to_shared(p);
}
__device__ __forceinline__ void cpa4(unsigned d, const float* s, int sz) {
    asm volatile("cp.async.ca.shared.global [%0], [%1], 4, %2;"
                 :: "r"(d), "l"(s), "r"(sz));
}
__device__ __forceinline__ void cpa16(unsigned d, const float* s, int sz) {
    asm volatile("cp.async.cg.shared.global [%0], [%1], 16, %2;"
                 :: "r"(d), "l"(s), "r"(sz));
}
__device__ __forceinline__ void cpa_commit() {
    asm volatile("cp.async.commit_group;");
}

// ------- weight transpose: [co][ci][r] -> [ci][r][stride] with offset -------
__global__ void transp_k(const float* __restrict__ src, float* __restrict__ dst,
                         int Cout, int Cin, int KK, int stride, int off)
{
    const int idx = blockIdx.x * blockDim.x + threadIdx.x;
    const int total = Cout * Cin * KK;
    if (idx >= total) return;
    const int co  = idx / (Cin * KK);
    const int rem = idx - co * (Cin * KK);
    dst[(size_t)rem * stride + off + co] = src[idx];
}

// ---------------- generic direct conv, 2 rows/block, cp.async pipeline ------
// block = 128 threads, TM=64 out-ch x TN=32 px x 2 rows; thread tile
// 4co x 4px x 2rows, co-pairs packed in f32x2. Double-buffered cp.async
// staging overlaps next chunk's loads with current chunk's FFMA2 stream.
// Vectorized float4 epilogue (rm-outer, rn-gathered).
// MINB = min blocks/SM hint (5 for low-reg shapes, 4 for reg-critical ones).
// ACT: 0 none, 1 relu, 2 sigmoid, 3 GRU blend (1-z)*hprev + z*tanh(v),
// 4 split: co<128 -> sigmoid -> outp (z); co>=128 -> sigmoid*hprev -> outp2 (r*h).
constexpr int TM = 64, TN = 32;

template<int KH, int KW, int ACT, int MINB>
__global__ __launch_bounds__(128, MINB)
void conv_k(const float* __restrict__ in0, int c0,
            const float* __restrict__ in1, int c1,
            const float* __restrict__ in2, int c2,
            const float* __restrict__ wt,    // transposed [ci][khkw][Cout]
            const float* __restrict__ bias,
            const float* __restrict__ bias2,
            const float* __restrict__ pre,
            const float* __restrict__ zbuf,
            const float* __restrict__ hprev,
            float* __restrict__ outp,
            float* __restrict__ outp2, int Cout, int Cin)
{
    constexpr int KK  = KH * KW;
    constexpr int CK  = (KK > 25) ? 1 : 8;
    constexpr int PH  = KH / 2;
    constexpr int PW  = KW / 2;
    constexpr int WIN = 4 + KW - 1;
    constexpr int NW4 = (WIN + 3) / 4;
    constexpr int TNP = 28 + NW4 * 4;
    constexpr int NR  = KH + 1;

    __shared__ __align__(16) float s_w [2][CK * KK * TM];
    __shared__ __align__(16) float s_in[2][CK * NR * TNP];

    const int b      = blockIdx.z;
    const int cotile = blockIdx.y;
    const int tile   = blockIdx.x;
    const int y0     = (tile / (WW / TN)) * 2;
    const int x0     = (tile % (WW / TN)) * TN;

    const int tid = threadIdx.x;
    const int tco = tid >> 3;     // 0..15
    const int tpx = tid & 7;      // 0..7
    const int cob = cotile * TM;

    // -------- stage one chunk into buffer `buf` via cp.async --------
    auto stage = [&](int ci0, int buf) {
        const float* src; int ct, cl;
        if (ci0 < c0)           { src = in0; ct = c0; cl = ci0;           }
        else if (ci0 < c0 + c1) { src = in1; ct = c1; cl = ci0 - c0;      }
        else                    { src = in2; ct = c2; cl = ci0 - c0 - c1; }
        const float* sb = src + ((size_t)b * ct + cl) * PLANE;
        // inputs: CK channels x NR rows x TNP cols, 4B each, zero-fill OOB
        for (int i = tid; i < CK * NR * TNP; i += 128) {
            const int ci  = i / (NR * TNP);
            const int rem = i - ci * (NR * TNP);
            const int rr  = rem / TNP;
            const int j   = rem - rr * TNP;
            const int yy  = y0 - PH + rr;
            const int xx  = x0 - PW + j;
            const bool inb = (yy >= 0 && yy < HH && xx >= 0 && xx < WW);
            const size_t o = inb ? ((size_t)ci * PLANE + yy * WW + xx) : 0;
            cpa4(smaddr(&s_in[buf][i]), sb + o, inb ? 4 : 0);
        }
        // weights: CK*KK rows of TM, 16B each, zero-fill past Cout
        for (int i4 = tid; i4 < CK * KK * (TM / 4); i4 += 128) {
            const int co4 = (i4 & 15) * 4;
            const int r   = i4 >> 4;
            const int gco = cob + co4;
            const float* wrow = wt + ((size_t)ci0 * KK + r) * Cout + gco;
            cpa16(smaddr(&s_w[buf][r * TM + co4]), wrow, (gco < Cout) ? 16 : 0);
        }
        cpa_commit();
    };

    unsigned long long acc[2][4][2];
#pragma unroll
    for (int r = 0; r < 2; r++)
#pragma unroll
        for (int i = 0; i < 4; i++) { acc[r][i][0] = 0ull; acc[r][i][1] = 0ull; }

    const int nch = Cin / CK;
    stage(0, 0);

    for (int c = 0; c < nch; c++) {
        if (c + 1 < nch) {
            stage((c + 1) * CK, (c + 1) & 1);
            asm volatile("cp.async.wait_group 1;");
        } else {
            asm volatile("cp.async.wait_group 0;");
        }
        __syncthreads();

        const float* sw  = s_w [c & 1];
        const float* sin = s_in[c & 1];

        for (int ci = 0; ci < CK; ci++) {
            unsigned long long sp[2][WIN];
            {
                const float* ip = sin + (ci * NR + 0) * TNP + tpx * 4;
                float win[NW4 * 4];
#pragma unroll
                for (int w4 = 0; w4 < NW4; w4++)
                    *(float4*)(win + 4 * w4) = *(const float4*)(ip + 4 * w4);
#pragma unroll
                for (int j = 0; j < WIN; j++) sp[0][j] = splat2(win[j]);
            }
#pragma unroll
            for (int kh = 0; kh < KH; kh++) {
                {
                    const float* ip = sin + (ci * NR + kh + 1) * TNP + tpx * 4;
                    float win[NW4 * 4];
#pragma unroll
                    for (int w4 = 0; w4 < NW4; w4++)
                        *(float4*)(win + 4 * w4) = *(const float4*)(ip + 4 * w4);
#pragma unroll
                    for (int j = 0; j < WIN; j++) sp[(kh + 1) & 1][j] = splat2(win[j]);
                }
                const unsigned long long* s0 = sp[kh & 1];
                const unsigned long long* s1 = sp[(kh + 1) & 1];
#pragma unroll
                for (int kw = 0; kw < KW; kw++) {
                    const ulonglong2 wv = *(const ulonglong2*)
                        (sw + ((ci * KH + kh) * KW + kw) * TM + tco * 4);
#pragma unroll
                    for (int rn = 0; rn < 4; rn++) {
                        acc[0][rn][0] = fma2(wv.x, s0[kw + rn], acc[0][rn][0]);
                        acc[0][rn][1] = fma2(wv.y, s0[kw + rn], acc[0][rn][1]);
                        acc[1][rn][0] = fma2(wv.x, s1[kw + rn], acc[1][rn][0]);
                        acc[1][rn][1] = fma2(wv.y, s1[kw + rn], acc[1][rn][1]);
                    }
                }
            }
        }
        __syncthreads();
    }

    // -------- epilogue (2 rows, float4-vectorized; rm outer, rn gathered) ---
#pragma unroll
    for (int row = 0; row < 2; row++) {
        const int y   = y0 + row;
        const int pix = y * WW + x0 + tpx * 4;   // 16B-aligned base of 4 px
#pragma unroll
        for (int rm = 0; rm < 4; rm++) {
            const int co = cob + tco * 4 + rm;
            if (co >= Cout) continue;
            // gather this co's 4 pixel values from the acc pairs
            float vv[4];
#pragma unroll
            for (int rn = 0; rn < 4; rn++) {
                const unsigned long long a = acc[row][rn][rm >> 1];
                vv[rn] = (rm & 1) ? hi32(a) : lo32(a);
            }
            if (pre) {
                const float4 p4 = *(const float4*)
                    (pre + ((size_t)b * Cout + co) * PLANE + pix);
                vv[0] += p4.x; vv[1] += p4.y; vv[2] += p4.z; vv[3] += p4.w;
            }
            if (ACT == 4) {
                if (co < 128) {
                    const float bv = bias[co];
                    float4 o4;
                    o4.x = 1.f / (1.f + expf(-(vv[0] + bv)));
                    o4.y = 1.f / (1.f + expf(-(vv[1] + bv)));
                    o4.z = 1.f / (1.f + expf(-(vv[2] + bv)));
                    o4.w = 1.f / (1.f + expf(-(vv[3] + bv)));
                    *(float4*)(outp + ((size_t)b * 128 + co) * PLANE + pix) = o4;
                } else {
                    const float bv = bias2[co - 128];
                    const size_t hi = ((size_t)b * 128 + (co - 128)) * PLANE + pix;
                    const float4 h4 = *(const float4*)(hprev + hi);
                    float4 o4;
                    o4.x = h4.x / (1.f + expf(-(vv[0] + bv)));
                    o4.y = h4.y / (1.f + expf(-(vv[1] + bv)));
                    o4.z = h4.z / (1.f + expf(-(vv[2] + bv)));
                    o4.w = h4.w / (1.f + expf(-(vv[3] + bv)));
                    *(float4*)(outp2 + hi) = o4;          // r*h
                }
            } else {
                const float bv = bias ? bias[co] : 0.f;
                const size_t oi = ((size_t)b * Cout + co) * PLANE + pix;
                float4 o4;
                if (ACT == 1) {
                    o4.x = fmaxf(vv[0] + bv, 0.f);
                    o4.y = fmaxf(vv[1] + bv, 0.f);
                    o4.z = fmaxf(vv[2] + bv, 0.f);
                    o4.w = fmaxf(vv[3] + bv, 0.f);
                } else if (ACT == 2) {
                    o4.x = 1.f / (1.f + expf(-(vv[0] + bv)));
                    o4.y = 1.f / (1.f + expf(-(vv[1] + bv)));
                    o4.z = 1.f / (1.f + expf(-(vv[2] + bv)));
                    o4.w = 1.f / (1.f + expf(-(vv[3] + bv)));
                } else if (ACT == 3) {
                    const size_t hi = ((size_t)b * 128 + co) * PLANE + pix;
                    const float4 z4 = *(const float4*)(zbuf + hi);
                    const float4 h4 = *(const float4*)(hprev + hi);
                    o4.x = (1.f - z4.x) * h4.x + z4.x * tanhf(vv[0] + bv);
                    o4.y = (1.f - z4.y) * h4.y + z4.y * tanhf(vv[1] + bv);
                    o4.z = (1.f - z4.z) * h4.z + z4.z * tanhf(vv[2] + bv);
                    o4.w = (1.f - z4.w) * h4.w + z4.w * tanhf(vv[3] + bv);
                } else {
                    o4.x = vv[0] + bv; o4.y = vv[1] + bv;
                    o4.z = vv[2] + bv; o4.w = vv[3] + bv;
                }
                *(float4*)(outp + oi) = o4;
            }
        }
    }
}

// ---------------- init: uniform bins, cd midpoints --------------------------
__global__ void init_k(float* __restrict__ cd, float* __restrict__ bst,
                       float* __restrict__ bsp)
{
    const int p = blockIdx.x * blockDim.x + threadIdx.x;
    if (p >= NP) return;
    bst[p] = 0.f;
    bsp[p] = 5.f;
    const int b  = p / PLANE;
    const int pp = p - b * PLANE;
    float e = 0.f;
#pragma unroll
    for (int i = 0; i < 16; i++) {
        const float en = e + 5.f;
        cd[((size_t)b * 16 + i) * PLANE + pp] = 0.5f * (e + en);
        e = en;
    }
}

// ---------------- epilogue: softmax, stats, label, bin update ---------------
__device__ __forceinline__ float clip80(float v) {
    return fminf(fmaxf(v, 0.f), 80.f);
}

__global__ void epi_k(const float* __restrict__ lg, float* __restrict__ cd,
                      float* __restrict__ bst, float* __restrict__ bsp,
                      float* __restrict__ outp, int iter)
{
    const int p = blockIdx.x * blockDim.x + threadIdx.x;
    if (p >= NP) return;
    const int b  = p / PLANE;
    const int pp = p - b * PLANE;
    const float* l0 = lg + (size_t)b * 16 * PLANE + pp;
    float*       c0 = cd + (size_t)b * 16 * PLANE + pp;

    float l[16], c[16];
    float m = -1e30f;
#pragma unroll
    for (int i = 0; i < 16; i++) { l[i] = l0[i * PLANE]; m = fmaxf(m, l[i]); }
    float s = 0.f;
#pragma unroll
    for (int i = 0; i < 16; i++) { l[i] = expf(l[i] - m); s += l[i]; }
    const float inv = 1.f / s;
    float dr = 0.f;
#pragma unroll
    for (int i = 0; i < 16; i++) { c[i] = c0[i * PLANE]; dr += l[i] * inv * c[i]; }
    float var = 0.f;
#pragma unroll
    for (int i = 0; i < 16; i++) { const float d = c[i] - dr; var += l[i] * inv * d * d; }
    const float unc = sqrtf(var);

    const float st = bst[p], sp = bsp[p];
    int cnt = 0;
    float e = st;
#pragma unroll
    for (int i = 1; i <= 15; i++) { e += sp; cnt += (dr >= clip80(e)) ? 1 : 0; }
    e += sp;
    const int label = (dr >= clip80(e)) ? 0 : cnt;
    const float cs = c[label];

    outp[(0 * 6 + iter) * NP + p] = dr;
    outp[(1 * 6 + iter) * NP + p] = cs;
    outp[(2 * 6 + iter) * NP + p] = unc;

    const float nst = fmaxf(dr - 0.5f * unc, 0.f);
    const float nsp = unc * (1.f / 16.f);
    bst[p] = nst;
    bsp[p] = nsp;
    float ep   = clip80(nst);
    float ecur = nst;
#pragma unroll
    for (int i = 0; i < 16; i++) {
        ecur += nsp;
        const float ec = clip80(ecur);
        c0[i * PLANE] = 0.5f * (ep + ec);
        ep = ec;
    }
}

// ---------------- host ------------------------------------------------------
static void do_transp(const float* src, float* dst, int Cout, int Cin, int KK,
                      int stride, int off) {
    const int total = Cout * Cin * KK;
    transp_k<<<(total + 255) / 256, 256>>>(src, dst, Cout, Cin, KK, stride, off);
}

extern "C" void kernel_launch(void* const* d_in, const int* in_sizes, int n_in,
                              void* d_out, int out_size)
{
    (void)in_sizes; (void)n_in; (void)out_size;
    const float* ctx  = (const float*)d_in[1];
    const float* gruh = (const float*)d_in[2];
    const float* w_e1 = (const float*)d_in[3];  const float* b_e1 = (const float*)d_in[4];
    const float* w_e2 = (const float*)d_in[5];  const float* b_e2 = (const float*)d_in[6];
    const float* w_e3 = (const float*)d_in[7];  const float* b_e3 = (const float*)d_in[8];
    const float* w_e4 = (const float*)d_in[9];  const float* b_e4 = (const float*)d_in[10];
    const float* w_z1 = (const float*)d_in[11]; const float* b_z1 = (const float*)d_in[12];
    const float* w_r1 = (const float*)d_in[13]; const float* b_r1 = (const float*)d_in[14];
    const float* w_q1 = (const float*)d_in[15]; const float* b_q1 = (const float*)d_in[16];
    const float* w_z2 = (const float*)d_in[17]; const float* b_z2 = (const float*)d_in[18];
    const float* w_r2 = (const float*)d_in[19]; const float* b_r2 = (const float*)d_in[20];
    const float* w_q2 = (const float*)d_in[21]; const float* b_q2 = (const float*)d_in[22];
    const float* w_p1 = (const float*)d_in[23]; const float* b_p1 = (const float*)d_in[24];
    const float* w_p2 = (const float*)d_in[25]; const float* b_p2 = (const float*)d_in[26];

    float *cd, *bst, *bsp, *t1, *t2, *dd, *ha, *hb, *zb, *rb, *pb, *wt;
    float *pzr1, *pq1, *pzr2, *pq2;
    cudaGetSymbolAddress((void**)&cd,  g_cd);
    cudaGetSymbolAddress((void**)&bst, g_bst);
    cudaGetSymbolAddress((void**)&bsp, g_bsp);
    cudaGetSymbolAddress((void**)&t1,  g_t1);
    cudaGetSymbolAddress((void**)&t2,  g_t2);
    cudaGetSymbolAddress((void**)&dd,  g_dd);
    cudaGetSymbolAddress((void**)&ha,  g_ha);
    cudaGetSymbolAddress((void**)&hb,  g_hb);
    cudaGetSymbolAddress((void**)&zb,  g_zb);
    cudaGetSymbolAddress((void**)&rb,  g_rb);
    cudaGetSymbolAddress((void**)&pb,  g_pb);
    cudaGetSymbolAddress((void**)&wt,  g_wt);
    cudaGetSymbolAddress((void**)&pzr1, g_pzr1);
    cudaGetSymbolAddress((void**)&pq1,  g_pq1);
    cudaGetSymbolAddress((void**)&pzr2, g_pzr2);
    cudaGetSymbolAddress((void**)&pq2,  g_pq2);
    float* out = (float*)d_out;

    // weight transposes (z/r interleaved into stride-256 regions)
    do_transp(w_e1, wt + OFF_E1, 128, 16, 49, 128, 0);
    do_transp(w_e2, wt + OFF_E2, 128, 128, 9, 128, 0);
    do_transp(w_e3, wt + OFF_E3, 128, 128, 9, 128, 0);
    do_transp(w_e4, wt + OFF_E4, 256, 128, 9, 256, 0);
    do_transp(w_z1, wt + OFF_ZR1, 128, 576, 5, 256, 0);
    do_transp(w_r1, wt + OFF_ZR1, 128, 576, 5, 256, 128);
    do_transp(w_q1, wt + OFF_Q1, 128, 576, 5, 128, 0);
    do_transp(w_z2, wt + OFF_ZR2, 128, 576, 5, 256, 0);
    do_transp(w_r2, wt + OFF_ZR2, 128, 576, 5, 256, 128);
    do_transp(w_q2, wt + OFF_Q2, 128, 576, 5, 128, 0);
    do_transp(w_p1, wt + OFF_P1, 128, 128, 9, 128, 0);
    do_transp(w_p2, wt + OFF_P2, 16, 128, 9, 16, 0);

    cudaMemcpyAsync(ha, gruh, sizeof(float) * BATCH * 128 * PLANE,
                    cudaMemcpyDeviceToDevice, 0);
    init_k<<<(NP + 255) / 256, 256>>>(cd, bst, bsp);

    // grid: 5 x-tiles * 60 row-pairs = 300
    const dim3 g1(300, 1, BATCH), g2(300, 2, BATCH), g4(300, 4, BATCH);

    // ---- loop-invariant ctx partial sums (192 of the 576 GRU channels) ----
    conv_k<1, 5, 0, 4><<<g4, 128>>>(ctx, 192, nullptr, 0, nullptr, 0,
                                 wt + OFF_ZR1 + (size_t)384 * 5 * 256,
                                 nullptr, nullptr, nullptr, nullptr, nullptr,
                                 pzr1, nullptr, 256, 192);
    conv_k<1, 5, 0, 4><<<g2, 128>>>(ctx, 192, nullptr, 0, nullptr, 0,
                                 wt + OFF_Q1 + (size_t)384 * 5 * 128,
                                 nullptr, nullptr, nullptr, nullptr, nullptr,
                                 pq1, nullptr, 128, 192);
    conv_k<5, 1, 0, 5><<<g4, 128>>>(ctx, 192, nullptr, 0, nullptr, 0,
                                 wt + OFF_ZR2 + (size_t)384 * 5 * 256,
                                 nullptr, nullptr, nullptr, nullptr, nullptr,
                                 pzr2, nullptr, 256, 192);
    conv_k<5, 1, 0, 5><<<g2, 128>>>(ctx, 192, nullptr, 0, nullptr, 0,
                                 wt + OFF_Q2 + (size_t)384 * 5 * 128,
                                 nullptr, nullptr, nullptr, nullptr, nullptr,
                                 pq2, nullptr, 128, 192);

    for (int it = 0; it < 6; it++) {
        // depth encoder
        conv_k<7, 7, 1, 4><<<g2, 128>>>(cd, 16, nullptr, 0, nullptr, 0,
                                     wt + OFF_E1, b_e1, nullptr, nullptr,
                                     nullptr, nullptr, t1, nullptr, 128, 16);
        conv_k<3, 3, 1, 5><<<g2, 128>>>(t1, 128, nullptr, 0, nullptr, 0,
                                     wt + OFF_E2, b_e2, nullptr, nullptr,
                                     nullptr, nullptr, t2, nullptr, 128, 128);
        conv_k<3, 3, 1, 5><<<g2, 128>>>(t2, 128, nullptr, 0, nullptr, 0,
                                     wt + OFF_E3, b_e3, nullptr, nullptr,
                                     nullptr, nullptr, t1, nullptr, 128, 128);
        conv_k<3, 3, 1, 5><<<g4, 128>>>(t1, 128, nullptr, 0, nullptr, 0,
                                     wt + OFF_E4, b_e4, nullptr, nullptr,
                                     nullptr, nullptr, dd, nullptr, 256, 128);
        // GRU horizontal (1x5): fused z|r (r*h written to rb), then q
        conv_k<1, 5, 4, 4><<<g4, 128>>>(ha, 128, dd, 256, nullptr, 0,
                                     wt + OFF_ZR1, b_z1, b_r1, pzr1,
                                     nullptr, ha, zb, rb, 256, 384);
        conv_k<1, 5, 3, 4><<<g2, 128>>>(rb, 128, dd, 256, nullptr, 0,
                                     wt + OFF_Q1, b_q1, nullptr, pq1,
                                     zb, ha, hb, nullptr, 128, 384);
        // GRU vertical (5x1): reads hb, writes ha
        conv_k<5, 1, 4, 5><<<g4, 128>>>(hb, 128, dd, 256, nullptr, 0,
                                     wt + OFF_ZR2, b_z2, b_r2, pzr2,
                                     nullptr, hb, zb, rb, 256, 384);
        conv_k<5, 1, 3, 5><<<g2, 128>>>(rb, 128, dd, 256, nullptr, 0,
                                     wt + OFF_Q2, b_q2, nullptr, pq2,
                                     zb, hb, ha, nullptr, 128, 384);
        // PHead
        conv_k<3, 3, 1, 5><<<g2, 128>>>(ha, 128, nullptr, 0, nullptr, 0,
                                     wt + OFF_P1, b_p1, nullptr, nullptr,
                                     nullptr, nullptr, t1, nullptr, 128, 128);
        conv_k<3, 3, 0, 5><<<g1, 128>>>(t1, 128, nullptr, 0, nullptr, 0,
                                     wt + OFF_P2, b_p2, nullptr, nullptr,
                                     nullptr, nullptr, pb, nullptr, 16, 128);
        epi_k<<<(NP + 255) / 256, 256>>>(pb, cd, bst, bsp, out, it);
    }
}

// round 12
// speedup vs baseline: 1.8999x; 1.0017x over previous
#include <cuda_runtime.h>
#include <math.h>

// Problem constants (fixed by setup_inputs)
#define BATCH 2
#define HH    120
#define WW    160
#define PLANE (HH*WW)          // 19200
#define NP    (BATCH*PLANE)    // 38400

// ---------------- scratch (device globals; no allocation allowed) ----------
__device__ float g_cd [BATCH*16 *PLANE];
__device__ float g_bst[NP];
__device__ float g_bsp[NP];
__device__ float g_t1 [BATCH*128*PLANE];
__device__ float g_t2 [BATCH*128*PLANE];
__device__ float g_dd [BATCH*256*PLANE];
__device__ float g_ha [BATCH*128*PLANE];
__device__ float g_hb [BATCH*128*PLANE];
__device__ float g_zb [BATCH*128*PLANE];
__device__ float g_rb [BATCH*128*PLANE];   // holds r*h after fused zr kernel
__device__ float g_pb [BATCH*16 *PLANE];
// precomputed context partial sums (loop-invariant)
__device__ float g_pzr1[BATCH*256*PLANE];
__device__ float g_pq1 [BATCH*128*PLANE];
__device__ float g_pzr2[BATCH*256*PLANE];
__device__ float g_pq2 [BATCH*128*PLANE];
// transposed weights, layout [ci][khkw][coStride], one region per conv
__device__ __align__(16) float g_wt[3067904];

// region offsets inside g_wt (floats)
#define OFF_E1  0
#define OFF_E2  100352
#define OFF_E3  247808
#define OFF_E4  395264
#define OFF_ZR1 690176      // z1|r1 interleaved, stride 256
#define OFF_Q1  1427456
#define OFF_ZR2 1796096     // z2|r2 interleaved, stride 256
#define OFF_Q2  2533376
#define OFF_P1  2902016
#define OFF_P2  3049472

// ---------------- f32x2 / cp.async helpers ---------------------------------
__device__ __forceinline__ unsigned long long fma2(unsigned long long a,
                                                   unsigned long long b,
                                                   unsigned long long c) {
    unsigned long long d;
    asm("fma.rn.f32x2 %0, %1, %2, %3;" : "=l"(d) : "l"(a), "l"(b), "l"(c));
    return d;
}
__device__ __forceinline__ unsigned long long splat2(float x) {
    unsigned long long d;
    asm("mov.b64 %0, {%1, %1};" : "=l"(d) : "f"(x));
    return d;
}
__device__ __forceinline__ float lo32(unsigned long long v) {
    return __uint_as_float((unsigned)(v & 0xffffffffull));
}
__device__ __forceinline__ float hi32(unsigned long long v) {
    return __uint_as_float((unsigned)(v >> 32));
}
__device__ __forceinline__ unsigned smaddr(const void* p) {
    return (unsigned)__cvta_generic_to_shared(p);
}
__device__ __forceinline__ void cpa4(unsigned d, const float* s, int sz) {
    asm volatile("cp.async.ca.shared.global [%0], [%1], 4, %2;"
                 :: "r"(d), "l"(s), "r"(sz));
}
__device__ __forceinline__ void cpa16(unsigned d, const float* s, int sz) {
    asm volatile("cp.async.cg.shared.global [%0], [%1], 16, %2;"
                 :: "r"(d), "l"(s), "r"(sz));
}
__device__ __forceinline__ void cpa_commit() {
    asm volatile("cp.async.commit_group;");
}

// ------- weight transpose: [co][ci][r] -> [ci][r][stride] with offset -------
__global__ void transp_k(const float* __restrict__ src, float* __restrict__ dst,
                         int Cout, int Cin, int KK, int stride, int off)
{
    const int idx = blockIdx.x * blockDim.x + threadIdx.x;
    const int total = Cout * Cin * KK;
    if (idx >= total) return;
    const int co  = idx / (Cin * KK);
    const int rem = idx - co * (Cin * KK);
    dst[(size_t)rem * stride + off + co] = src[idx];
}

// ---------------- generic direct conv, 2 rows/block, cp.async pipeline ------
// block = 128 threads, TM=64 out-ch x TN=32 px x 2 rows; thread tile
// 4co x 4px x 2rows, co-pairs packed in f32x2. Double-buffered cp.async
// staging overlaps next chunk's loads with current chunk's FFMA2 stream.
// Vectorized float4 epilogue (rm-outer, rn-gathered).
// MINB = min blocks/SM hint (5 for low-reg shapes, 4 for reg-critical ones).
// ACT: 0 none, 1 relu, 2 sigmoid, 3 GRU blend (1-z)*hprev + z*tanh(v),
// 4 split: co<128 -> sigmoid -> outp (z); co>=128 -> sigmoid*hprev -> outp2 (r*h).
constexpr int TM = 64, TN = 32;

template<int KH, int KW, int ACT, int MINB>
__global__ __launch_bounds__(128, MINB)
void conv_k(const float* __restrict__ in0, int c0,
            const float* __restrict__ in1, int c1,
            const float* __restrict__ in2, int c2,
            const float* __restrict__ wt,    // transposed [ci][khkw][Cout]
            const float* __restrict__ bias,
            const float* __restrict__ bias2,
            const float* __restrict__ pre,
            const float* __restrict__ zbuf,
            const float* __restrict__ hprev,
            float* __restrict__ outp,
            float* __restrict__ outp2, int Cout, int Cin)
{
    constexpr int KK  = KH * KW;
    constexpr int CK  = (KK > 25) ? 1 : 8;
    constexpr int PH  = KH / 2;
    constexpr int PW  = KW / 2;
    constexpr int WIN = 4 + KW - 1;
    constexpr int NW4 = (WIN + 3) / 4;
    constexpr int TNP = 28 + NW4 * 4;
    constexpr int NR  = KH + 1;

    __shared__ __align__(16) float s_w [2][CK * KK * TM];
    __shared__ __align__(16) float s_in[2][CK * NR * TNP];

    const int b      = blockIdx.z;
    const int cotile = blockIdx.y;
    const int tile   = blockIdx.x;
    const int y0     = (tile / (WW / TN)) * 2;
    const int x0     = (tile % (WW / TN)) * TN;

    const int tid = threadIdx.x;
    const int tco = tid >> 3;     // 0..15
    const int tpx = tid & 7;      // 0..7
    const int cob = cotile * TM;

    // -------- stage one chunk into buffer `buf` via cp.async --------
    auto stage = [&](int ci0, int buf) {
        const float* src; int ct, cl;
        if (ci0 < c0)           { src = in0; ct = c0; cl = ci0;           }
        else if (ci0 < c0 + c1) { src = in1; ct = c1; cl = ci0 - c0;      }
        else                    { src = in2; ct = c2; cl = ci0 - c0 - c1; }
        const float* sb = src + ((size_t)b * ct + cl) * PLANE;
        // inputs: CK channels x NR rows x TNP cols, 4B each, zero-fill OOB
        for (int i = tid; i < CK * NR * TNP; i += 128) {
            const int ci  = i / (NR * TNP);
            const int rem = i - ci * (NR * TNP);
            const int rr  = rem / TNP;
            const int j   = rem - rr * TNP;
            const int yy  = y0 - PH + rr;
            const int xx  = x0 - PW + j;
            const bool inb = (yy >= 0 && yy < HH && xx >= 0 && xx < WW);
            const size_t o = inb ? ((size_t)ci * PLANE + yy * WW + xx) : 0;
            cpa4(smaddr(&s_in[buf][i]), sb + o, inb ? 4 : 0);
        }
        // weights: CK*KK rows of TM, 16B each, zero-fill past Cout
        for (int i4 = tid; i4 < CK * KK * (TM / 4); i4 += 128) {
            const int co4 = (i4 & 15) * 4;
            const int r   = i4 >> 4;
            const int gco = cob + co4;
            const float* wrow = wt + ((size_t)ci0 * KK + r) * Cout + gco;
            cpa16(smaddr(&s_w[buf][r * TM + co4]), wrow, (gco < Cout) ? 16 : 0);
        }
        cpa_commit();
    };

    unsigned long long acc[2][4][2];
#pragma unroll
    for (int r = 0; r < 2; r++)
#pragma unroll
        for (int i = 0; i < 4; i++) { acc[r][i][0] = 0ull; acc[r][i][1] = 0ull; }

    const int nch = Cin / CK;
    stage(0, 0);

    for (int c = 0; c < nch; c++) {
        if (c + 1 < nch) {
            stage((c + 1) * CK, (c + 1) & 1);
            asm volatile("cp.async.wait_group 1;");
        } else {
            asm volatile("cp.async.wait_group 0;");
        }
        __syncthreads();

        const float* sw  = s_w [c & 1];
        const float* sin = s_in[c & 1];

        for (int ci = 0; ci < CK; ci++) {
            unsigned long long sp[2][WIN];
            {
                const float* ip = sin + (ci * NR + 0) * TNP + tpx * 4;
                float win[NW4 * 4];
#pragma unroll
                for (int w4 = 0; w4 < NW4; w4++)
                    *(float4*)(win + 4 * w4) = *(const float4*)(ip + 4 * w4);
#pragma unroll
                for (int j = 0; j < WIN; j++) sp[0][j] = splat2(win[j]);
            }
#pragma unroll
            for (int kh = 0; kh < KH; kh++) {
                {
                    const float* ip = sin + (ci * NR + kh + 1) * TNP + tpx * 4;
                    float win[NW4 * 4];
#pragma unroll
                    for (int w4 = 0; w4 < NW4; w4++)
                        *(float4*)(win + 4 * w4) = *(const float4*)(ip + 4 * w4);
#pragma unroll
                    for (int j = 0; j < WIN; j++) sp[(kh + 1) & 1][j] = splat2(win[j]);
                }
                const unsigned long long* s0 = sp[kh & 1];
                const unsigned long long* s1 = sp[(kh + 1) & 1];
#pragma unroll
                for (int kw = 0; kw < KW; kw++) {
                    const ulonglong2 wv = *(const ulonglong2*)
                        (sw + ((ci * KH + kh) * KW + kw) * TM + tco * 4);
#pragma unroll
                    for (int rn = 0; rn < 4; rn++) {
                        acc[0][rn][0] = fma2(wv.x, s0[kw + rn], acc[0][rn][0]);
                        acc[0][rn][1] = fma2(wv.y, s0[kw + rn], acc[0][rn][1]);
                        acc[1][rn][0] = fma2(wv.x, s1[kw + rn], acc[1][rn][0]);
                        acc[1][rn][1] = fma2(wv.y, s1[kw + rn], acc[1][rn][1]);
                    }
                }
            }
        }
        __syncthreads();
    }

    // -------- epilogue (2 rows, float4-vectorized; rm outer, rn gathered) ---
#pragma unroll
    for (int row = 0; row < 2; row++) {
        const int y   = y0 + row;
        const int pix = y * WW + x0 + tpx * 4;   // 16B-aligned base of 4 px
#pragma unroll
        for (int rm = 0; rm < 4; rm++) {
            const int co = cob + tco * 4 + rm;
            if (co >= Cout) continue;
            // gather this co's 4 pixel values from the acc pairs
            float vv[4];
#pragma unroll
            for (int rn = 0; rn < 4; rn++) {
                const unsigned long long a = acc[row][rn][rm >> 1];
                vv[rn] = (rm & 1) ? hi32(a) : lo32(a);
            }
            if (pre) {
                const float4 p4 = *(const float4*)
                    (pre + ((size_t)b * Cout + co) * PLANE + pix);
                vv[0] += p4.x; vv[1] += p4.y; vv[2] += p4.z; vv[3] += p4.w;
            }
            if (ACT == 4) {
                if (co < 128) {
                    const float bv = bias[co];
                    float4 o4;
                    o4.x = 1.f / (1.f + expf(-(vv[0] + bv)));
                    o4.y = 1.f / (1.f + expf(-(vv[1] + bv)));
                    o4.z = 1.f / (1.f + expf(-(vv[2] + bv)));
                    o4.w = 1.f / (1.f + expf(-(vv[3] + bv)));
                    *(float4*)(outp + ((size_t)b * 128 + co) * PLANE + pix) = o4;
                } else {
                    const float bv = bias2[co - 128];
                    const size_t hi = ((size_t)b * 128 + (co - 128)) * PLANE + pix;
                    const float4 h4 = *(const float4*)(hprev + hi);
                    float4 o4;
                    o4.x = h4.x / (1.f + expf(-(vv[0] + bv)));
                    o4.y = h4.y / (1.f + expf(-(vv[1] + bv)));
                    o4.z = h4.z / (1.f + expf(-(vv[2] + bv)));
                    o4.w = h4.w / (1.f + expf(-(vv[3] + bv)));
                    *(float4*)(outp2 + hi) = o4;          // r*h
                }
            } else {
                const float bv = bias ? bias[co] : 0.f;
                const size_t oi = ((size_t)b * Cout + co) * PLANE + pix;
                float4 o4;
                if (ACT == 1) {
                    o4.x = fmaxf(vv[0] + bv, 0.f);
                    o4.y = fmaxf(vv[1] + bv, 0.f);
                    o4.z = fmaxf(vv[2] + bv, 0.f);
                    o4.w = fmaxf(vv[3] + bv, 0.f);
                } else if (ACT == 2) {
                    o4.x = 1.f / (1.f + expf(-(vv[0] + bv)));
                    o4.y = 1.f / (1.f + expf(-(vv[1] + bv)));
                    o4.z = 1.f / (1.f + expf(-(vv[2] + bv)));
                    o4.w = 1.f / (1.f + expf(-(vv[3] + bv)));
                } else if (ACT == 3) {
                    const size_t hi = ((size_t)b * 128 + co) * PLANE + pix;
                    const float4 z4 = *(const float4*)(zbuf + hi);
                    const float4 h4 = *(const float4*)(hprev + hi);
                    o4.x = (1.f - z4.x) * h4.x + z4.x * tanhf(vv[0] + bv);
                    o4.y = (1.f - z4.y) * h4.y + z4.y * tanhf(vv[1] + bv);
                    o4.z = (1.f - z4.z) * h4.z + z4.z * tanhf(vv[2] + bv);
                    o4.w = (1.f - z4.w) * h4.w + z4.w * tanhf(vv[3] + bv);
                } else {
                    o4.x = vv[0] + bv; o4.y = vv[1] + bv;
                    o4.z = vv[2] + bv; o4.w = vv[3] + bv;
                }
                *(float4*)(outp + oi) = o4;
            }
        }
    }
}

// ---------------- init: uniform bins, cd midpoints --------------------------
__global__ void init_k(float* __restrict__ cd, float* __restrict__ bst,
                       float* __restrict__ bsp)
{
    const int p = blockIdx.x * blockDim.x + threadIdx.x;
    if (p >= NP) return;
    bst[p] = 0.f;
    bsp[p] = 5.f;
    const int b  = p / PLANE;
    const int pp = p - b * PLANE;
    float e = 0.f;
#pragma unroll
    for (int i = 0; i < 16; i++) {
        const float en = e + 5.f;
        cd[((size_t)b * 16 + i) * PLANE + pp] = 0.5f * (e + en);
        e = en;
    }
}

// ---------------- epilogue: softmax, stats, label, bin update ---------------
__device__ __forceinline__ float clip80(float v) {
    return fminf(fmaxf(v, 0.f), 80.f);
}

__global__ void epi_k(const float* __restrict__ lg, float* __restrict__ cd,
                      float* __restrict__ bst, float* __restrict__ bsp,
                      float* __restrict__ outp, int iter)
{
    const int p = blockIdx.x * blockDim.x + threadIdx.x;
    if (p >= NP) return;
    const int b  = p / PLANE;
    const int pp = p - b * PLANE;
    const float* l0 = lg + (size_t)b * 16 * PLANE + pp;
    float*       c0 = cd + (size_t)b * 16 * PLANE + pp;

    float l[16], c[16];
    float m = -1e30f;
#pragma unroll
    for (int i = 0; i < 16; i++) { l[i] = l0[i * PLANE]; m = fmaxf(m, l[i]); }
    float s = 0.f;
#pragma unroll
    for (int i = 0; i < 16; i++) { l[i] = expf(l[i] - m); s += l[i]; }
    const float inv = 1.f / s;
    float dr = 0.f;
#pragma unroll
    for (int i = 0; i < 16; i++) { c[i] = c0[i * PLANE]; dr += l[i] * inv * c[i]; }
    float var = 0.f;
#pragma unroll
    for (int i = 0; i < 16; i++) { const float d = c[i] - dr; var += l[i] * inv * d * d; }
    const float unc = sqrtf(var);

    const float st = bst[p], sp = bsp[p];
    int cnt = 0;
    float e = st;
#pragma unroll
    for (int i = 1; i <= 15; i++) { e += sp; cnt += (dr >= clip80(e)) ? 1 : 0; }
    e += sp;
    const int label = (dr >= clip80(e)) ? 0 : cnt;
    const float cs = c[label];

    outp[(0 * 6 + iter) * NP + p] = dr;
    outp[(1 * 6 + iter) * NP + p] = cs;
    outp[(2 * 6 + iter) * NP + p] = unc;

    const float nst = fmaxf(dr - 0.5f * unc, 0.f);
    const float nsp = unc * (1.f / 16.f);
    bst[p] = nst;
    bsp[p] = nsp;
    float ep   = clip80(nst);
    float ecur = nst;
#pragma unroll
    for (int i = 0; i < 16; i++) {
        ecur += nsp;
        const float ec = clip80(ecur);
        c0[i * PLANE] = 0.5f * (ep + ec);
        ep = ec;
    }
}

// ---------------- host ------------------------------------------------------
static void do_transp(const float* src, float* dst, int Cout, int Cin, int KK,
                      int stride, int off) {
    const int total = Cout * Cin * KK;
    transp_k<<<(total + 255) / 256, 256>>>(src, dst, Cout, Cin, KK, stride, off);
}

extern "C" void kernel_launch(void* const* d_in, const int* in_sizes, int n_in,
                              void* d_out, int out_size)
{
    (void)in_sizes; (void)n_in; (void)out_size;
    const float* ctx  = (const float*)d_in[1];
    const float* gruh = (const float*)d_in[2];
    const float* w_e1 = (const float*)d_in[3];  const float* b_e1 = (const float*)d_in[4];
    const float* w_e2 = (const float*)d_in[5];  const float* b_e2 = (const float*)d_in[6];
    const float* w_e3 = (const float*)d_in[7];  const float* b_e3 = (const float*)d_in[8];
    const float* w_e4 = (const float*)d_in[9];  const float* b_e4 = (const float*)d_in[10];
    const float* w_z1 = (const float*)d_in[11]; const float* b_z1 = (const float*)d_in[12];
    const float* w_r1 = (const float*)d_in[13]; const float* b_r1 = (const float*)d_in[14];
    const float* w_q1 = (const float*)d_in[15]; const float* b_q1 = (const float*)d_in[16];
    const float* w_z2 = (const float*)d_in[17]; const float* b_z2 = (const float*)d_in[18];
    const float* w_r2 = (const float*)d_in[19]; const float* b_r2 = (const float*)d_in[20];
    const float* w_q2 = (const float*)d_in[21]; const float* b_q2 = (const float*)d_in[22];
    const float* w_p1 = (const float*)d_in[23]; const float* b_p1 = (const float*)d_in[24];
    const float* w_p2 = (const float*)d_in[25]; const float* b_p2 = (const float*)d_in[26];

    float *cd, *bst, *bsp, *t1, *t2, *dd, *ha, *hb, *zb, *rb, *pb, *wt;
    float *pzr1, *pq1, *pzr2, *pq2;
    cudaGetSymbolAddress((void**)&cd,  g_cd);
    cudaGetSymbolAddress((void**)&bst, g_bst);
    cudaGetSymbolAddress((void**)&bsp, g_bsp);
    cudaGetSymbolAddress((void**)&t1,  g_t1);
    cudaGetSymbolAddress((void**)&t2,  g_t2);
    cudaGetSymbolAddress((void**)&dd,  g_dd);
    cudaGetSymbolAddress((void**)&ha,  g_ha);
    cudaGetSymbolAddress((void**)&hb,  g_hb);
    cudaGetSymbolAddress((void**)&zb,  g_zb);
    cudaGetSymbolAddress((void**)&rb,  g_rb);
    cudaGetSymbolAddress((void**)&pb,  g_pb);
    cudaGetSymbolAddress((void**)&wt,  g_wt);
    cudaGetSymbolAddress((void**)&pzr1, g_pzr1);
    cudaGetSymbolAddress((void**)&pq1,  g_pq1);
    cudaGetSymbolAddress((void**)&pzr2, g_pzr2);
    cudaGetSymbolAddress((void**)&pq2,  g_pq2);
    float* out = (float*)d_out;

    // weight transposes (z/r interleaved into stride-256 regions)
    do_transp(w_e1, wt + OFF_E1, 128, 16, 49, 128, 0);
    do_transp(w_e2, wt + OFF_E2, 128, 128, 9, 128, 0);
    do_transp(w_e3, wt + OFF_E3, 128, 128, 9, 128, 0);
    do_transp(w_e4, wt + OFF_E4, 256, 128, 9, 256, 0);
    do_transp(w_z1, wt + OFF_ZR1, 128, 576, 5, 256, 0);
    do_transp(w_r1, wt + OFF_ZR1, 128, 576, 5, 256, 128);
    do_transp(w_q1, wt + OFF_Q1, 128, 576, 5, 128, 0);
    do_transp(w_z2, wt + OFF_ZR2, 128, 576, 5, 256, 0);
    do_transp(w_r2, wt + OFF_ZR2, 128, 576, 5, 256, 128);
    do_transp(w_q2, wt + OFF_Q2, 128, 576, 5, 128, 0);
    do_transp(w_p1, wt + OFF_P1, 128, 128, 9, 128, 0);
    do_transp(w_p2, wt + OFF_P2, 16, 128, 9, 16, 0);

    cudaMemcpyAsync(ha, gruh, sizeof(float) * BATCH * 128 * PLANE,
                    cudaMemcpyDeviceToDevice, 0);
    init_k<<<(NP + 255) / 256, 256>>>(cd, bst, bsp);

    // grid: 5 x-tiles * 60 row-pairs = 300
    const dim3 g1(300, 1, BATCH), g2(300, 2, BATCH), g4(300, 4, BATCH);

    // ---- loop-invariant ctx partial sums (192 of the 576 GRU channels) ----
    conv_k<1, 5, 0, 4><<<g4, 128>>>(ctx, 192, nullptr, 0, nullptr, 0,
                                 wt + OFF_ZR1 + (size_t)384 * 5 * 256,
                                 nullptr, nullptr, nullptr, nullptr, nullptr,
                                 pzr1, nullptr, 256, 192);
    conv_k<1, 5, 0, 4><<<g2, 128>>>(ctx, 192, nullptr, 0, nullptr, 0,
                                 wt + OFF_Q1 + (size_t)384 * 5 * 128,
                                 nullptr, nullptr, nullptr, nullptr, nullptr,
                                 pq1, nullptr, 128, 192);
    conv_k<5, 1, 0, 5><<<g4, 128>>>(ctx, 192, nullptr, 0, nullptr, 0,
                                 wt + OFF_ZR2 + (size_t)384 * 5 * 256,
                                 nullptr, nullptr, nullptr, nullptr, nullptr,
                                 pzr2, nullptr, 256, 192);
    conv_k<5, 1, 0, 5><<<g2, 128>>>(ctx, 192, nullptr, 0, nullptr, 0,
                                 wt + OFF_Q2 + (size_t)384 * 5 * 128,
                                 nullptr, nullptr, nullptr, nullptr, nullptr,
                                 pq2, nullptr, 128, 192);

    for (int it = 0; it < 6; it++) {
        // depth encoder
        conv_k<7, 7, 1, 4><<<g2, 128>>>(cd, 16, nullptr, 0, nullptr, 0,
                                     wt + OFF_E1, b_e1, nullptr, nullptr,
                                     nullptr, nullptr, t1, nullptr, 128, 16);
        conv_k<3, 3, 1, 5><<<g2, 128>>>(t1, 128, nullptr, 0, nullptr, 0,
                                     wt + OFF_E2, b_e2, nullptr, nullptr,
                                     nullptr, nullptr, t2, nullptr, 128, 128);
        conv_k<3, 3, 1, 5><<<g2, 128>>>(t2, 128, nullptr, 0, nullptr, 0,
                                     wt + OFF_E3, b_e3, nullptr, nullptr,
                                     nullptr, nullptr, t1, nullptr, 128, 128);
        conv_k<3, 3, 1, 5><<<g4, 128>>>(t1, 128, nullptr, 0, nullptr, 0,
                                     wt + OFF_E4, b_e4, nullptr, nullptr,
                                     nullptr, nullptr, dd, nullptr, 256, 128);
        // GRU horizontal (1x5): fused z|r (r*h written to rb), then q
        conv_k<1, 5, 4, 4><<<g4, 128>>>(ha, 128, dd, 256, nullptr, 0,
                                     wt + OFF_ZR1, b_z1, b_r1, pzr1,
                                     nullptr, ha, zb, rb, 256, 384);
        conv_k<1, 5, 3, 4><<<g2, 128>>>(rb, 128, dd, 256, nullptr, 0,
                                     wt + OFF_Q1, b_q1, nullptr, pq1,
                                     zb, ha, hb, nullptr, 128, 384);
        // GRU vertical (5x1): reads hb, writes ha
        conv_k<5, 1, 4, 5><<<g4, 128>>>(hb, 128, dd, 256, nullptr, 0,
                                     wt + OFF_ZR2, b_z2, b_r2, pzr2,
                                     nullptr, hb, zb, rb, 256, 384);
        conv_k<5, 1, 3, 5><<<g2, 128>>>(rb, 128, dd, 256, nullptr, 0,
                                     wt + OFF_Q2, b_q2, nullptr, pq2,
                                     zb, hb, ha, nullptr, 128, 384);
        // PHead
        conv_k<3, 3, 1, 5><<<g2, 128>>>(ha, 128, nullptr, 0, nullptr, 0,
                                     wt + OFF_P1, b_p1, nullptr, nullptr,
                                     nullptr, nullptr, t1, nullptr, 128, 128);
        conv_k<3, 3, 0, 5><<<g1, 128>>>(t1, 128, nullptr, 0, nullptr, 0,
                                     wt + OFF_P2, b_p2, nullptr, nullptr,
                                     nullptr, nullptr, pb, nullptr, 16, 128);
        epi_k<<<(NP + 255) / 256, 256>>>(pb, cd, bst, bsp, out, it);
    }
}